// round 10
// baseline (speedup 1.0000x reference)
#include <cuda_runtime.h>
#include <cstdint>

// CausalConv1d: y[b,l,d] = bias[d] + sum_{k=0..3} x[b, l-3+k, d] * w[d,0,k]
// x: (B=8, L=4096, D=1024) fp32, D innermost. w: (D,1,4). b: (D,). Out: (B,L,D).
//
// Steady-state limiter is y WRITEBACK competing with next replay's reads:
// y (134MB) nearly fits L2 (126MB). Pin y in L2 (evict_last store policy) so
// each replay re-dirties resident lines and writebacks mostly never reach
// DRAM; stream x with evict_first so it can't displace y. Compute structure
// identical to R8: 512 blocks x 64 rows, 8-row batched LDG.128 (MLP=8).

#define CC_B 8
#define CC_L 4096
#define CC_D 1024
#define CC_DV (CC_D / 4)             // 256 float4 lanes over D
#define CC_LC 64                     // rows per block
#define CC_TILE 8                    // rows per load batch
#define CC_NCHUNK (CC_L / CC_LC)     // 64
#define CC_GRID (CC_B * CC_NCHUNK)   // 512

__device__ __forceinline__ float4 ldg_pol(const float4* p, uint64_t pol) {
    float4 v;
    asm("ld.global.nc.L2::cache_hint.v4.f32 {%0,%1,%2,%3}, [%4], %5;"
        : "=f"(v.x), "=f"(v.y), "=f"(v.z), "=f"(v.w)
        : "l"(p), "l"(pol));
    return v;
}
__device__ __forceinline__ void stg_pol(float4* p, float4 v, uint64_t pol) {
    asm volatile("st.global.L2::cache_hint.v4.f32 [%0], {%1,%2,%3,%4}, %5;"
        :: "l"(p), "f"(v.x), "f"(v.y), "f"(v.z), "f"(v.w), "l"(pol)
        : "memory");
}

__global__ __launch_bounds__(CC_DV, 2)
void causal_conv1d_kernel(const float4* __restrict__ x,
                          const float4* __restrict__ w4,
                          const float4* __restrict__ bias,
                          float4*       __restrict__ y)
{
    const int d4    = threadIdx.x;           // 0..255
    const int chunk = blockIdx.x & (CC_NCHUNK - 1);
    const int b     = blockIdx.x >> 6;
    const int l0    = chunk * CC_LC;

    // L2 policies: x streams (evict_first), y persists (evict_last).
    uint64_t pol_x, pol_y;
    asm("createpolicy.fractional.L2::evict_first.b64 %0, 1.0;" : "=l"(pol_x));
    asm("createpolicy.fractional.L2::evict_last.b64 %0, 1.0;"  : "=l"(pol_y));

    // Weights: (D,1,4) -> per-thread 16 contiguous floats = 4 float4s;
    // cN = taps 0..3 of channel d0+N. Transpose to per-tap vectors.
    const float4 c0 = w4[d4 * 4 + 0];
    const float4 c1 = w4[d4 * 4 + 1];
    const float4 c2 = w4[d4 * 4 + 2];
    const float4 c3 = w4[d4 * 4 + 3];
    const float4 wk0 = make_float4(c0.x, c1.x, c2.x, c3.x);
    const float4 wk1 = make_float4(c0.y, c1.y, c2.y, c3.y);
    const float4 wk2 = make_float4(c0.z, c1.z, c2.z, c3.z);
    const float4 wk3 = make_float4(c0.w, c1.w, c2.w, c3.w);

    const float4 bv = bias[d4];

    const size_t rowbase = (size_t)(b * CC_L + l0) * CC_DV + d4;

    // v[0..2] = sliding window (x[l-3..l-1]); v[3..10] = current 8-row tile.
    float4 v[CC_TILE + 3];
    if (l0 == 0) {
        v[0] = make_float4(0.f, 0.f, 0.f, 0.f);
        v[1] = v[0];
        v[2] = v[0];
    } else {
        v[0] = ldg_pol(x + rowbase - 3 * CC_DV, pol_x);
        v[1] = ldg_pol(x + rowbase - 2 * CC_DV, pol_x);
        v[2] = ldg_pol(x + rowbase - 1 * CC_DV, pol_x);
    }

    #pragma unroll
    for (int t = 0; t < CC_LC / CC_TILE; t++) {
        const size_t tb = rowbase + (size_t)(t * CC_TILE) * CC_DV;

        // Batch-issue 8 independent LDG.128s (MLP=8) before any consumer.
        #pragma unroll
        for (int i = 0; i < CC_TILE; i++)
            v[3 + i] = ldg_pol(x + tb + (size_t)i * CC_DV, pol_x);

        // Compute + store 8 rows (y pinned in L2 via evict_last).
        #pragma unroll
        for (int i = 0; i < CC_TILE; i++) {
            const float4 a3 = v[i], a2 = v[i + 1], a1 = v[i + 2], a0 = v[i + 3];
            float4 r;
            r.x = fmaf(wk0.x, a3.x, fmaf(wk1.x, a2.x, fmaf(wk2.x, a1.x, fmaf(wk3.x, a0.x, bv.x))));
            r.y = fmaf(wk0.y, a3.y, fmaf(wk1.y, a2.y, fmaf(wk2.y, a1.y, fmaf(wk3.y, a0.y, bv.y))));
            r.z = fmaf(wk0.z, a3.z, fmaf(wk1.z, a2.z, fmaf(wk2.z, a1.z, fmaf(wk3.z, a0.z, bv.z))));
            r.w = fmaf(wk0.w, a3.w, fmaf(wk1.w, a2.w, fmaf(wk2.w, a1.w, fmaf(wk3.w, a0.w, bv.w))));
            stg_pol(y + tb + (size_t)i * CC_DV, r, pol_y);
        }

        // Roll window: last 3 rows of this tile feed the next tile.
        v[0] = v[CC_TILE];
        v[1] = v[CC_TILE + 1];
        v[2] = v[CC_TILE + 2];
    }
}

extern "C" void kernel_launch(void* const* d_in, const int* in_sizes, int n_in,
                              void* d_out, int out_size)
{
    (void)in_sizes; (void)n_in; (void)out_size;
    const float4* x    = (const float4*)d_in[0];
    const float4* w4   = (const float4*)d_in[1];
    const float4* bias = (const float4*)d_in[2];
    float4*       y    = (float4*)d_out;

    causal_conv1d_kernel<<<CC_GRID, CC_DV>>>(x, w4, bias, y);
}

// round 12
// speedup vs baseline: 1.0315x; 1.0315x over previous
#include <cuda_runtime.h>

// CausalConv1d: y[b,l,d] = bias[d] + sum_{k=0..3} x[b, l-3+k, d] * w[d,0,k]
// x: (B=8, L=4096, D=1024) fp32, D innermost. w: (D,1,4). b: (D,). Out: (B,L,D).
//
// At the mixed read/write DRAM ceiling. Measured: default L2 store policy
// beats __stcs (47.1 vs 48.5) and evict_last pinning (49.2). This round =
// R8 structure (LC=64 halves halo reads; weights as 4x LDG.128) with plain
// default stores. Core: 8-row batched LDG.128 tiles (MLP=8), <=128 regs,
// 2 CTAs/SM, 512 blocks.

#define CC_B 8
#define CC_L 4096
#define CC_D 1024
#define CC_DV (CC_D / 4)             // 256 float4 lanes over D
#define CC_LC 64                     // rows per block
#define CC_TILE 8                    // rows per load batch
#define CC_NCHUNK (CC_L / CC_LC)     // 64
#define CC_GRID (CC_B * CC_NCHUNK)   // 512

__global__ __launch_bounds__(CC_DV, 2)
void causal_conv1d_kernel(const float4* __restrict__ x,
                          const float4* __restrict__ w4,
                          const float4* __restrict__ bias,
                          float4*       __restrict__ y)
{
    const int d4    = threadIdx.x;           // 0..255
    const int chunk = blockIdx.x & (CC_NCHUNK - 1);
    const int b     = blockIdx.x >> 6;
    const int l0    = chunk * CC_LC;

    // Weights: (D,1,4) -> per-thread 16 contiguous floats = 4 float4s;
    // cN = taps 0..3 of channel d0+N. Transpose to per-tap vectors.
    const float4 c0 = w4[d4 * 4 + 0];
    const float4 c1 = w4[d4 * 4 + 1];
    const float4 c2 = w4[d4 * 4 + 2];
    const float4 c3 = w4[d4 * 4 + 3];
    const float4 wk0 = make_float4(c0.x, c1.x, c2.x, c3.x);  // tap 0, chans 0..3
    const float4 wk1 = make_float4(c0.y, c1.y, c2.y, c3.y);  // tap 1
    const float4 wk2 = make_float4(c0.z, c1.z, c2.z, c3.z);  // tap 2
    const float4 wk3 = make_float4(c0.w, c1.w, c2.w, c3.w);  // tap 3

    const float4 bv = bias[d4];

    const size_t rowbase = (size_t)(b * CC_L + l0) * CC_DV + d4;

    // v[0..2] = sliding window (x[l-3..l-1]); v[3..10] = current 8-row tile.
    float4 v[CC_TILE + 3];
    if (l0 == 0) {
        v[0] = make_float4(0.f, 0.f, 0.f, 0.f);
        v[1] = v[0];
        v[2] = v[0];
    } else {
        v[0] = x[rowbase - 3 * CC_DV];
        v[1] = x[rowbase - 2 * CC_DV];
        v[2] = x[rowbase - 1 * CC_DV];
    }

    #pragma unroll
    for (int t = 0; t < CC_LC / CC_TILE; t++) {
        const size_t tb = rowbase + (size_t)(t * CC_TILE) * CC_DV;

        // Batch-issue 8 independent LDG.128s (MLP=8) before any consumer.
        #pragma unroll
        for (int i = 0; i < CC_TILE; i++)
            v[3 + i] = x[tb + (size_t)i * CC_DV];

        // Compute + store 8 rows (default L2 policy — measured best).
        #pragma unroll
        for (int i = 0; i < CC_TILE; i++) {
            const float4 a3 = v[i], a2 = v[i + 1], a1 = v[i + 2], a0 = v[i + 3];
            float4 r;
            r.x = fmaf(wk0.x, a3.x, fmaf(wk1.x, a2.x, fmaf(wk2.x, a1.x, fmaf(wk3.x, a0.x, bv.x))));
            r.y = fmaf(wk0.y, a3.y, fmaf(wk1.y, a2.y, fmaf(wk2.y, a1.y, fmaf(wk3.y, a0.y, bv.y))));
            r.z = fmaf(wk0.z, a3.z, fmaf(wk1.z, a2.z, fmaf(wk2.z, a1.z, fmaf(wk3.z, a0.z, bv.z))));
            r.w = fmaf(wk0.w, a3.w, fmaf(wk1.w, a2.w, fmaf(wk2.w, a1.w, fmaf(wk3.w, a0.w, bv.w))));
            y[tb + (size_t)i * CC_DV] = r;
        }

        // Roll window: last 3 rows of this tile feed the next tile.
        v[0] = v[CC_TILE];
        v[1] = v[CC_TILE + 1];
        v[2] = v[CC_TILE + 2];
    }
}

extern "C" void kernel_launch(void* const* d_in, const int* in_sizes, int n_in,
                              void* d_out, int out_size)
{
    (void)in_sizes; (void)n_in; (void)out_size;
    const float4* x    = (const float4*)d_in[0];
    const float4* w4   = (const float4*)d_in[1];
    const float4* bias = (const float4*)d_in[2];
    float4*       y    = (float4*)d_out;

    causal_conv1d_kernel<<<CC_GRID, CC_DV>>>(x, w4, bias, y);
}